// round 13
// baseline (speedup 1.0000x reference)
#include <cuda_runtime.h>
#include <cuda_bf16.h>
#include <cuda_fp16.h>
#include <math.h>

#define Bn 4
#define Qn 1024
#define Dn 256
#define GH 64
#define TQ 64
#define TK 64
#define PITCH 72    // bf16 pitch for mma smem tiles
#define BPITCH 66   // fp32 pitch for bil staging

typedef unsigned int uint;

__device__ __nv_bfloat16 g_qWb[Bn * Qn * Dn];
__device__ __nv_bfloat16 g_qb[Bn * Qn * Dn];

__device__ __forceinline__ uint packbf2(float lo, float hi) {
    uint r;
    asm("cvt.rn.bf16x2.f32 %0, %1, %2;" : "=r"(r) : "f"(hi), "f"(lo));
    return r;
}

__device__ __forceinline__ uint packh2(float lo, float hi) {
    uint r;
    asm("cvt.rn.f16x2.f32 %0, %1, %2;" : "=r"(r) : "f"(hi), "f"(lo));
    return r;
}

// packed silu on f16x2: x * sigmoid(x); 1 MUFU for 2 lanes.
__device__ __forceinline__ uint silu2h(uint x) {
    const uint H = 0x38003800u;   // f16x2 (0.5, 0.5)
    uint t;
    asm("mul.rn.f16x2 %0, %1, %2;" : "=r"(t) : "r"(x), "r"(H));
    asm("tanh.approx.f16x2 %0, %1;" : "=r"(t) : "r"(t));
    asm("fma.rn.f16x2 %0, %1, %2, %3;" : "=r"(t) : "r"(t), "r"(H), "r"(H));
    uint r;
    asm("mul.rn.f16x2 %0, %1, %2;" : "=r"(r) : "r"(x), "r"(t));
    return r;
}

#define HFMA2H(d, a, b, c) \
    asm("fma.rn.f16x2 %0, %1, %2, %3;" : "=r"(d) : "r"(a), "r"(b), "r"(c))

__device__ __forceinline__ float hsum2(uint p) {
    float2 f = __half22float2(*(__half2*)&p);
    return f.x + f.y;
}

// bf16, f32-acc (bilinear / prep)
__device__ __forceinline__ void mma16816(float* c, uint a0, uint a1, uint a2, uint a3,
                                         uint b0, uint b1) {
    asm("mma.sync.aligned.m16n8k16.row.col.f32.bf16.bf16.f32 "
        "{%0,%1,%2,%3},{%4,%5,%6,%7},{%8,%9},{%0,%1,%2,%3};"
        : "+f"(c[0]), "+f"(c[1]), "+f"(c[2]), "+f"(c[3])
        : "r"(a0), "r"(a1), "r"(a2), "r"(a3), "r"(b0), "r"(b1));
}

// f16, f16-acc (MLP)
__device__ __forceinline__ void mma16816h(uint& d0, uint& d1,
                                          uint a0, uint a1, uint a2, uint a3,
                                          uint b0, uint b1) {
    asm("mma.sync.aligned.m16n8k16.row.col.f16.f16.f16.f16 "
        "{%0,%1},{%2,%3,%4,%5},{%6,%7},{%0,%1};"
        : "+r"(d0), "+r"(d1)
        : "r"(a0), "r"(a1), "r"(a2), "r"(a3), "r"(b0), "r"(b1));
}

__device__ __forceinline__ void mma16808h(uint& d0, uint& d1,
                                          uint a0, uint a1, uint b0) {
    asm("mma.sync.aligned.m16n8k8.row.col.f16.f16.f16.f16 "
        "{%0,%1},{%2,%3},{%4},{%0,%1};"
        : "+r"(d0), "+r"(d1)
        : "r"(a0), "r"(a1), "r"(b0));
}

// ---------------------------------------------------------------------------
// Fused prep kernel: qW = q @ W via mma; writes g_qWb (bf16); bn==0 blocks
// side-write g_qb. (unchanged from R12)
// ---------------------------------------------------------------------------
__global__ __launch_bounds__(256) void prep_kernel(
    const float* __restrict__ q, const float* __restrict__ W)
{
    __shared__ __align__(16) __nv_bfloat16 At[64 * PITCH];
    __shared__ __align__(16) __nv_bfloat16 Bt[64 * PITCH];
    __shared__ __align__(16) float Ws[64][68];

    const int tid  = threadIdx.x;
    const int warp = tid >> 5;
    const int lane = tid & 31;
    const int m    = lane & 3;
    const int g    = lane >> 2;
    const int wq   = warp & 3;
    const int wk   = warp >> 2;
    const int bm   = blockIdx.x * 64;
    const int bn   = blockIdx.y * 64;

    float bacc[4][4];
#pragma unroll
    for (int n = 0; n < 4; n++)
#pragma unroll
        for (int j = 0; j < 4; j++) bacc[n][j] = 0.f;

#pragma unroll 1
    for (int k0 = 0; k0 < Dn; k0 += 64) {
        __syncthreads();
#pragma unroll
        for (int rep = 0; rep < 4; rep++) {
            int idx = rep * 256 + tid;
            int r = idx >> 4, c4 = idx & 15;
            float4 v = *(const float4*)&q[(bm + r) * Dn + k0 + c4 * 4];
            uint2 o;
            o.x = packbf2(v.x, v.y);
            o.y = packbf2(v.z, v.w);
            *(uint2*)&At[r * PITCH + c4 * 4] = o;
            if (bn == 0)
                *(uint2*)&g_qb[(bm + r) * Dn + k0 + c4 * 4] = o;
        }
#pragma unroll
        for (int rep = 0; rep < 4; rep++) {
            int idx = rep * 256 + tid;
            int kr = idx >> 4, nc4 = idx & 15;
            float4 w = *(const float4*)&W[(k0 + kr) * Dn + bn + nc4 * 4];
            *(float4*)&Ws[kr][nc4 * 4] = w;
        }
        __syncthreads();
#pragma unroll
        for (int rep = 0; rep < 8; rep++) {
            int idx = rep * 256 + tid;
            int nc = idx & 63, kp = idx >> 6;
            uint v = packbf2(Ws[2 * kp][nc], Ws[2 * kp + 1][nc]);
            *(uint*)&Bt[nc * PITCH + 2 * kp] = v;
        }
        __syncthreads();
#pragma unroll
        for (int s2 = 0; s2 < 4; s2++) {
            const int acol = 16 * s2 + 2 * m;
            const int arow = 16 * wq + g;
            uint a0 = *(const uint*)&At[arow * PITCH + acol];
            uint a1 = *(const uint*)&At[(arow + 8) * PITCH + acol];
            uint a2 = *(const uint*)&At[arow * PITCH + acol + 8];
            uint a3 = *(const uint*)&At[(arow + 8) * PITCH + acol + 8];
#pragma unroll
            for (int n = 0; n < 4; n++) {
                const int brow = 32 * wk + 8 * n + g;
                uint b0 = *(const uint*)&Bt[brow * PITCH + acol];
                uint b1 = *(const uint*)&Bt[brow * PITCH + acol + 8];
                mma16816(bacc[n], a0, a1, a2, a3, b0, b1);
            }
        }
    }
#pragma unroll
    for (int n = 0; n < 4; n++) {
        int row = bm + 16 * wq + g;
        int col = bn + 32 * wk + 8 * n + 2 * m;
        *(__nv_bfloat162*)&g_qWb[row * Dn + col] =
            __floats2bfloat162_rn(bacc[n][0], bacc[n][1]);
        *(__nv_bfloat162*)&g_qWb[(row + 8) * Dn + col] =
            __floats2bfloat162_rn(bacc[n][2], bacc[n][3]);
    }
}

// ---------------------------------------------------------------------------
// Fused kernel: bilinear (bf16 mma) + geo MLP (f16-acc mma, dual-k B reuse).
// ---------------------------------------------------------------------------
__global__ __launch_bounds__(256, 2) void edge_head_mma_kernel(
    const float* __restrict__ coords,
    const int*   __restrict__ amask,
    const float* __restrict__ w1,
    const float* __restrict__ b1,
    const float* __restrict__ w2,
    const float* __restrict__ b2,
    const float* __restrict__ w3,
    const float* __restrict__ b3,
    const float* __restrict__ bias,
    float* __restrict__ out)
{
    // union region: bilinear tiles (18432B) / GA feature table (16384B)
    __shared__ __align__(16) char uraw[TQ * PITCH * 2 + TK * PITCH * 2];
    __shared__ float  bilS[TQ * BPITCH];
    __shared__ __align__(16) uint4 B4s[4 * 4 * 32];   // layer-2 f16 B frag pairs
    __shared__ uint   b1ph[32], b2ph[32], w3ph[32];   // f16x2 packs [nb*4+m]
    __shared__ float  cxq[TQ], cyq[TQ], cxk[TK], cyk[TK];
    __shared__ int    aqs[TQ], aks[TK];
    __shared__ float  cadd;

    __nv_bfloat16* qWt = (__nv_bfloat16*)uraw;
    __nv_bfloat16* qt  = (__nv_bfloat16*)(uraw + TQ * PITCH * 2);
    uint*          GAs = (uint*)uraw;     // [16 k][64 row][4] f16x2 feature pairs

    const int tid  = threadIdx.x;
    const int warp = tid >> 5;
    const int lane = tid & 31;
    const int m    = lane & 3;
    const int g    = lane >> 2;
    const int wq   = warp & 3;
    const int wk   = warp >> 2;
    const int b    = blockIdx.z;
    const int q0   = blockIdx.y * TQ;
    const int k0   = blockIdx.x * TK;

    // ---- prewrite whole out tile to -1e9 (inactive entries keep this) ----
    {
        const float4 neg = make_float4(-1e9f, -1e9f, -1e9f, -1e9f);
#pragma unroll
        for (int e = tid; e < 1024; e += 256) {
            int r = e >> 4, c = (e & 15) * 4;
            *(float4*)&out[((long)(b * Qn + q0 + r)) * Qn + k0 + c] = neg;
        }
    }

    if (tid < GH) {
        int i = tid;
        int gq = b * Qn + q0 + i;
        cxq[i] = coords[gq * 2 + 0]; cyq[i] = coords[gq * 2 + 1];
        aqs[i] = amask[gq];
    } else if (tid < 2 * GH) {
        int i = tid - GH;
        int gk = b * Qn + k0 + i;
        cxk[i] = coords[gk * 2 + 0]; cyk[i] = coords[gk * 2 + 1];
        aks[i] = amask[gk];
    }
    if (tid == 0) cadd = b3[0] + bias[0];

    // layer-2 B fragment pairs (f16): entry (s, np, lane) -> frags n=2np, 2np+1
#pragma unroll
    for (int e = tid; e < 512; e += 256) {
        int s  = e >> 7;
        int np = (e >> 5) & 3;
        int ln = e & 31;
        int em = ln & 3, eg = ln >> 2;
        int kk = 16 * s + 2 * em;
        uint4 v;
        int n0 = 8 * (2 * np) + eg;
        v.x = packh2(w2[kk * GH + n0],       w2[(kk + 1) * GH + n0]);
        v.y = packh2(w2[(kk + 8) * GH + n0], w2[(kk + 9) * GH + n0]);
        int n1 = 8 * (2 * np + 1) + eg;
        v.z = packh2(w2[kk * GH + n1],       w2[(kk + 1) * GH + n1]);
        v.w = packh2(w2[(kk + 8) * GH + n1], w2[(kk + 9) * GH + n1]);
        B4s[e] = v;
    }
    if (tid < 32) {
        int nb = tid >> 2, mm = tid & 3;
        int c = 8 * nb + 2 * mm;
        b1ph[tid] = packh2(b1[c], b1[c + 1]);
        b2ph[tid] = packh2(b2[c], b2[c + 1]);
        w3ph[tid] = packh2(w3[c], w3[c + 1]);
    }

    uint W1B[8];
#pragma unroll
    for (int nb = 0; nb < 8; nb++) {
        int nn = 8 * nb + g;
        W1B[nb] = (m < 3) ? packh2(w1[(2 * m) * GH + nn], w1[(2 * m + 1) * GH + nn]) : 0u;
    }

    // ---- bilinear via bf16 mma (unchanged) ----
    float bacc[4][4];
#pragma unroll
    for (int n = 0; n < 4; n++)
#pragma unroll
        for (int j = 0; j < 4; j++) bacc[n][j] = 0.f;

#pragma unroll 1
    for (int d0 = 0; d0 < Dn; d0 += 64) {
        __syncthreads();
#pragma unroll
        for (int rep = 0; rep < 2; rep++) {
            int idx = tid + rep * 256;
            int r = idx >> 3, c8 = (idx & 7) * 8;
            *(uint4*)&qWt[r * PITCH + c8] =
                *(const uint4*)&g_qWb[(b * Qn + q0 + r) * Dn + d0 + c8];
            *(uint4*)&qt[r * PITCH + c8] =
                *(const uint4*)&g_qb[(b * Qn + k0 + r) * Dn + d0 + c8];
        }
        __syncthreads();
#pragma unroll
        for (int s2 = 0; s2 < 4; s2++) {
            const int acol = 16 * s2 + 2 * m;
            const int arow = 16 * wq + g;
            uint a0 = *(const uint*)&qWt[arow * PITCH + acol];
            uint a1 = *(const uint*)&qWt[(arow + 8) * PITCH + acol];
            uint a2 = *(const uint*)&qWt[arow * PITCH + acol + 8];
            uint a3 = *(const uint*)&qWt[(arow + 8) * PITCH + acol + 8];
#pragma unroll
            for (int n = 0; n < 4; n++) {
                const int brow = 32 * wk + 8 * n + g;
                uint b0 = *(const uint*)&qt[brow * PITCH + acol];
                uint b1v = *(const uint*)&qt[brow * PITCH + acol + 8];
                mma16816(bacc[n], a0, a1, a2, a3, b0, b1v);
            }
        }
    }
    __syncthreads();
#pragma unroll
    for (int n = 0; n < 4; n++) {
        int row = 16 * wq + g;
        int col = 32 * wk + 8 * n + 2 * m;
        *(float2*)&bilS[row * BPITCH + col]       = make_float2(bacc[n][0], bacc[n][1]);
        *(float2*)&bilS[(row + 8) * BPITCH + col] = make_float2(bacc[n][2], bacc[n][3]);
    }

    // ---- MLP phase: 4 passes; per-warp active-k pairing; f16 dual-k mma ----
    const int row0 = 16 * wq + g;
    const int row1 = row0 + 8;
    const bool qa0 = (aqs[row0] != 0), qa1 = (aqs[row1] != 0);
    const float caddv = cadd;

#pragma unroll 1
    for (int p = 0; p < 4; p++) {
        __syncthreads();   // prior GA/tile reads done before overwrite
        // GA features (f16x2) for k in [16p, 16p+16), all 64 rows
#pragma unroll
        for (int r = 0; r < 4; r++) {
            int e   = tid + 256 * r;
            int kl  = e >> 6;
            int row = e & 63;
            int k   = 16 * p + kl;
            if (aks[k] != 0) {
                float dxv = cxq[row] - cxk[k];
                float dyv = cyq[row] - cyk[k];
                float d2v = fmaf(dxv, dxv, dyv * dyv);
                float dsv = sqrtf(d2v + 1e-8f);
                bool  mzv = (fabsf(dxv) < 1e-6f) && (fabsf(dyv) < 1e-6f);
                float xsv = mzv ? 1e-6f : dxv;
                float ysv = mzv ? 1e-6f : dyv;
                float rhv = rsqrtf(fmaf(xsv, xsv, ysv * ysv));
                uint4 gv;
                gv.x = packh2(dxv, dyv);
                gv.y = packh2(dsv, d2v);
                gv.z = packh2(ysv * rhv, xsv * rhv);
                gv.w = 0u;
                *(uint4*)&GAs[(kl * 64 + row) * 4] = gv;
            }
        }
        __syncthreads();

        // active-k bitmask for this warp's 8 k's (warp-uniform)
        uint kmask = 0u;
#pragma unroll
        for (int i = 0; i < 8; i++)
            kmask |= (aks[16 * p + 8 * wk + i] != 0 ? 1u : 0u) << i;

        while (kmask) {
            const int ia = __ffs((int)kmask) - 1;
            kmask &= kmask - 1u;
            const bool dual = (kmask != 0u);
            const int ib = dual ? (__ffs((int)kmask) - 1) : ia;
            if (dual) kmask &= kmask - 1u;

            const int kla = 8 * wk + ia;       // GA slot (tile k - 16p)
            const int klb = 8 * wk + ib;
            const int ka  = 16 * p + kla;      // tile-local k
            const int kb  = 16 * p + klb;

            const uint A0a = GAs[(kla * 64 + row0) * 4 + m];
            const uint A1a = GAs[(kla * 64 + row1) * 4 + m];
            const uint A0b = GAs[(klb * 64 + row0) * 4 + m];
            const uint A1b = GAs[(klb * 64 + row1) * 4 + m];

            uint acca[8][2], accb[8][2];
#pragma unroll
            for (int n = 0; n < 8; n++) {
                uint bv = b2ph[n * 4 + m];
                acca[n][0] = bv; acca[n][1] = bv;
                accb[n][0] = bv; accb[n][1] = bv;
            }

#pragma unroll
            for (int s = 0; s < 4; s++) {
                const uint bb0 = b1ph[(2 * s) * 4 + m];
                const uint bb1 = b1ph[(2 * s + 1) * 4 + m];
                // layer-1 both k's (f16 acc, outputs pre-packed pairs)
                uint d0 = bb0, d1 = bb0;
                mma16808h(d0, d1, A0a, A1a, W1B[2 * s]);
                uint e0 = bb1, e1 = bb1;
                mma16808h(e0, e1, A0a, A1a, W1B[2 * s + 1]);
                uint a0 = silu2h(d0), a1 = silu2h(d1);
                uint a2 = silu2h(e0), a3 = silu2h(e1);

                uint f0 = bb0, f1 = bb0;
                mma16808h(f0, f1, A0b, A1b, W1B[2 * s]);
                uint h0 = bb1, h1 = bb1;
                mma16808h(h0, h1, A0b, A1b, W1B[2 * s + 1]);
                uint c0 = silu2h(f0), c1 = silu2h(f1);
                uint c2 = silu2h(h0), c3 = silu2h(h1);

                const uint4* Brow = &B4s[(s * 4) * 32 + lane];
#pragma unroll
                for (int np = 0; np < 4; np++) {
                    uint4 Bv = Brow[np * 32];       // shared by both k's
                    mma16816h(acca[2 * np][0],     acca[2 * np][1],
                              a0, a1, a2, a3, Bv.x, Bv.y);
                    mma16816h(acca[2 * np + 1][0], acca[2 * np + 1][1],
                              a0, a1, a2, a3, Bv.z, Bv.w);
                    mma16816h(accb[2 * np][0],     accb[2 * np][1],
                              c0, c1, c2, c3, Bv.x, Bv.y);
                    mma16816h(accb[2 * np + 1][0], accb[2 * np + 1][1],
                              c0, c1, c2, c3, Bv.z, Bv.w);
                }
            }

            // epilogue: packed silu(h2) . w3 (f16x2 accumulate)
            uint Pa0 = 0u, Pa1 = 0u, Pb0 = 0u, Pb1 = 0u;
#pragma unroll
            for (int n = 0; n < 8; n++) {
                uint wv = w3ph[n * 4 + m];
                uint sa0 = silu2h(acca[n][0]);
                uint sa1 = silu2h(acca[n][1]);
                uint sb0 = silu2h(accb[n][0]);
                uint sb1 = silu2h(accb[n][1]);
                HFMA2H(Pa0, sa0, wv, Pa0);
                HFMA2H(Pa1, sa1, wv, Pa1);
                HFMA2H(Pb0, sb0, wv, Pb0);
                HFMA2H(Pb1, sb1, wv, Pb1);
            }
            float pa0 = hsum2(Pa0), pa1 = hsum2(Pa1);
            float pb0 = hsum2(Pb0), pb1 = hsum2(Pb1);
            pa0 += __shfl_xor_sync(0xffffffffu, pa0, 1);
            pa0 += __shfl_xor_sync(0xffffffffu, pa0, 2);
            pa1 += __shfl_xor_sync(0xffffffffu, pa1, 1);
            pa1 += __shfl_xor_sync(0xffffffffu, pa1, 2);
            pb0 += __shfl_xor_sync(0xffffffffu, pb0, 1);
            pb0 += __shfl_xor_sync(0xffffffffu, pb0, 2);
            pb1 += __shfl_xor_sync(0xffffffffu, pb1, 1);
            pb1 += __shfl_xor_sync(0xffffffffu, pb1, 2);

            const int gka = k0 + ka;
            if (m == (ia & 3)) {
                const int qi0 = q0 + row0, qi1 = q0 + row1;
                if (qa0)
                    out[((long)(b * Qn + qi0)) * Qn + gka] =
                        (qi0 == gka) ? 0.f : pa0 + bilS[row0 * BPITCH + ka] + caddv;
                if (qa1)
                    out[((long)(b * Qn + qi1)) * Qn + gka] =
                        (qi1 == gka) ? 0.f : pa1 + bilS[row1 * BPITCH + ka] + caddv;
            }
            if (dual && m == (ib & 3)) {
                const int gkb = k0 + kb;
                const int qi0 = q0 + row0, qi1 = q0 + row1;
                if (qa0)
                    out[((long)(b * Qn + qi0)) * Qn + gkb] =
                        (qi0 == gkb) ? 0.f : pb0 + bilS[row0 * BPITCH + kb] + caddv;
                if (qa1)
                    out[((long)(b * Qn + qi1)) * Qn + gkb] =
                        (qi1 == gkb) ? 0.f : pb1 + bilS[row1 * BPITCH + kb] + caddv;
            }
        }
    }
}

// ---------------------------------------------------------------------------
extern "C" void kernel_launch(void* const* d_in, const int* in_sizes, int n_in,
                              void* d_out, int out_size)
{
    const float* q      = (const float*)d_in[0];
    const float* coords = (const float*)d_in[1];
    const int*   amask  = (const int*)d_in[2];
    const float* W      = (const float*)d_in[3];
    const float* w1     = (const float*)d_in[4];
    const float* b1     = (const float*)d_in[5];
    const float* w2     = (const float*)d_in[6];
    const float* b2     = (const float*)d_in[7];
    const float* w3     = (const float*)d_in[8];
    const float* b3     = (const float*)d_in[9];
    const float* bias   = (const float*)d_in[10];
    float* out = (float*)d_out;

    {
        dim3 grid((Bn * Qn) / 64, Dn / 64);
        prep_kernel<<<grid, 256>>>(q, W);
    }
    {
        dim3 grid(Qn / TK, Qn / TQ, Bn);
        edge_head_mma_kernel<<<grid, 256>>>(coords, amask,
                                            w1, b1, w2, b2, w3, b3, bias, out);
    }
}

// round 14
// speedup vs baseline: 1.3447x; 1.3447x over previous
#include <cuda_runtime.h>
#include <cuda_bf16.h>
#include <cuda_fp16.h>
#include <math.h>

#define Bn 4
#define Qn 1024
#define Dn 256
#define GH 64
#define TQ 64
#define TK 64
#define PITCH 72    // bf16 pitch for mma smem tiles
#define BPITCH 66   // fp32 pitch for bil staging

typedef unsigned int uint;

__device__ __nv_bfloat16 g_qWb[Bn * Qn * Dn];
__device__ __nv_bfloat16 g_qb[Bn * Qn * Dn];

__device__ __forceinline__ uint packbf2(float lo, float hi) {
    uint r;
    asm("cvt.rn.bf16x2.f32 %0, %1, %2;" : "=r"(r) : "f"(hi), "f"(lo));
    return r;
}

__device__ __forceinline__ uint packh2(float lo, float hi) {
    uint r;
    asm("cvt.rn.f16x2.f32 %0, %1, %2;" : "=r"(r) : "f"(hi), "f"(lo));
    return r;
}

// packed silu on f16x2: x * sigmoid(x); 1 MUFU for 2 lanes.
__device__ __forceinline__ uint silu2h(uint x) {
    const uint H = 0x38003800u;   // f16x2 (0.5, 0.5)
    uint t;
    asm("mul.rn.f16x2 %0, %1, %2;" : "=r"(t) : "r"(x), "r"(H));
    asm("tanh.approx.f16x2 %0, %1;" : "=r"(t) : "r"(t));
    asm("fma.rn.f16x2 %0, %1, %2, %3;" : "=r"(t) : "r"(t), "r"(H), "r"(H));
    uint r;
    asm("mul.rn.f16x2 %0, %1, %2;" : "=r"(r) : "r"(x), "r"(t));
    return r;
}

#define HFMA2H(d, a, b, c) \
    asm("fma.rn.f16x2 %0, %1, %2, %3;" : "=r"(d) : "r"(a), "r"(b), "r"(c))

__device__ __forceinline__ float hsum2(uint p) {
    float2 f = __half22float2(*(__half2*)&p);
    return f.x + f.y;
}

// bf16, f32-acc (bilinear / prep)
__device__ __forceinline__ void mma16816(float* c, uint a0, uint a1, uint a2, uint a3,
                                         uint b0, uint b1) {
    asm("mma.sync.aligned.m16n8k16.row.col.f32.bf16.bf16.f32 "
        "{%0,%1,%2,%3},{%4,%5,%6,%7},{%8,%9},{%0,%1,%2,%3};"
        : "+f"(c[0]), "+f"(c[1]), "+f"(c[2]), "+f"(c[3])
        : "r"(a0), "r"(a1), "r"(a2), "r"(a3), "r"(b0), "r"(b1));
}

// f16, f16-acc (MLP)
__device__ __forceinline__ void mma16816h(uint& d0, uint& d1,
                                          uint a0, uint a1, uint a2, uint a3,
                                          uint b0, uint b1) {
    asm("mma.sync.aligned.m16n8k16.row.col.f16.f16.f16.f16 "
        "{%0,%1},{%2,%3,%4,%5},{%6,%7},{%0,%1};"
        : "+r"(d0), "+r"(d1)
        : "r"(a0), "r"(a1), "r"(a2), "r"(a3), "r"(b0), "r"(b1));
}

__device__ __forceinline__ void mma16808h(uint& d0, uint& d1,
                                          uint a0, uint a1, uint b0) {
    asm("mma.sync.aligned.m16n8k8.row.col.f16.f16.f16.f16 "
        "{%0,%1},{%2,%3},{%4},{%0,%1};"
        : "+r"(d0), "+r"(d1)
        : "r"(a0), "r"(a1), "r"(b0));
}

// ---------------------------------------------------------------------------
// Fused prep kernel: qW = q @ W via mma; writes g_qWb (bf16); bn==0 blocks
// side-write g_qb. (unchanged from R12)
// ---------------------------------------------------------------------------
__global__ __launch_bounds__(256) void prep_kernel(
    const float* __restrict__ q, const float* __restrict__ W)
{
    __shared__ __align__(16) __nv_bfloat16 At[64 * PITCH];
    __shared__ __align__(16) __nv_bfloat16 Bt[64 * PITCH];
    __shared__ __align__(16) float Ws[64][68];

    const int tid  = threadIdx.x;
    const int warp = tid >> 5;
    const int lane = tid & 31;
    const int m    = lane & 3;
    const int g    = lane >> 2;
    const int wq   = warp & 3;
    const int wk   = warp >> 2;
    const int bm   = blockIdx.x * 64;
    const int bn   = blockIdx.y * 64;

    float bacc[4][4];
#pragma unroll
    for (int n = 0; n < 4; n++)
#pragma unroll
        for (int j = 0; j < 4; j++) bacc[n][j] = 0.f;

#pragma unroll 1
    for (int k0 = 0; k0 < Dn; k0 += 64) {
        __syncthreads();
#pragma unroll
        for (int rep = 0; rep < 4; rep++) {
            int idx = rep * 256 + tid;
            int r = idx >> 4, c4 = idx & 15;
            float4 v = *(const float4*)&q[(bm + r) * Dn + k0 + c4 * 4];
            uint2 o;
            o.x = packbf2(v.x, v.y);
            o.y = packbf2(v.z, v.w);
            *(uint2*)&At[r * PITCH + c4 * 4] = o;
            if (bn == 0)
                *(uint2*)&g_qb[(bm + r) * Dn + k0 + c4 * 4] = o;
        }
#pragma unroll
        for (int rep = 0; rep < 4; rep++) {
            int idx = rep * 256 + tid;
            int kr = idx >> 4, nc4 = idx & 15;
            float4 w = *(const float4*)&W[(k0 + kr) * Dn + bn + nc4 * 4];
            *(float4*)&Ws[kr][nc4 * 4] = w;
        }
        __syncthreads();
#pragma unroll
        for (int rep = 0; rep < 8; rep++) {
            int idx = rep * 256 + tid;
            int nc = idx & 63, kp = idx >> 6;
            uint v = packbf2(Ws[2 * kp][nc], Ws[2 * kp + 1][nc]);
            *(uint*)&Bt[nc * PITCH + 2 * kp] = v;
        }
        __syncthreads();
#pragma unroll
        for (int s2 = 0; s2 < 4; s2++) {
            const int acol = 16 * s2 + 2 * m;
            const int arow = 16 * wq + g;
            uint a0 = *(const uint*)&At[arow * PITCH + acol];
            uint a1 = *(const uint*)&At[(arow + 8) * PITCH + acol];
            uint a2 = *(const uint*)&At[arow * PITCH + acol + 8];
            uint a3 = *(const uint*)&At[(arow + 8) * PITCH + acol + 8];
#pragma unroll
            for (int n = 0; n < 4; n++) {
                const int brow = 32 * wk + 8 * n + g;
                uint b0 = *(const uint*)&Bt[brow * PITCH + acol];
                uint b1 = *(const uint*)&Bt[brow * PITCH + acol + 8];
                mma16816(bacc[n], a0, a1, a2, a3, b0, b1);
            }
        }
    }
#pragma unroll
    for (int n = 0; n < 4; n++) {
        int row = bm + 16 * wq + g;
        int col = bn + 32 * wk + 8 * n + 2 * m;
        *(__nv_bfloat162*)&g_qWb[row * Dn + col] =
            __floats2bfloat162_rn(bacc[n][0], bacc[n][1]);
        *(__nv_bfloat162*)&g_qWb[(row + 8) * Dn + col] =
            __floats2bfloat162_rn(bacc[n][2], bacc[n][3]);
    }
}

// ---------------------------------------------------------------------------
// Fused kernel: bilinear (bf16 mma) + geo MLP (f16-acc mma, R12 structure).
// ---------------------------------------------------------------------------
__global__ __launch_bounds__(256, 2) void edge_head_mma_kernel(
    const float* __restrict__ coords,
    const int*   __restrict__ amask,
    const float* __restrict__ w1,
    const float* __restrict__ b1,
    const float* __restrict__ w2,
    const float* __restrict__ b2,
    const float* __restrict__ w3,
    const float* __restrict__ b3,
    const float* __restrict__ bias,
    float* __restrict__ out)
{
    // union region: bilinear tiles (18432B) / GA feature table (16384B)
    __shared__ __align__(16) char uraw[TQ * PITCH * 2 + TK * PITCH * 2];
    __shared__ float  bilS[TQ * BPITCH];
    __shared__ __align__(16) uint4 B4s[4 * 4 * 32];   // layer-2 f16 B frag pairs
    __shared__ uint   b1ph[32], b2ph[32], w3ph[32];   // f16x2 packs [nb*4+m]
    __shared__ float  cxq[TQ], cyq[TQ], cxk[TK], cyk[TK];
    __shared__ int    aqs[TQ], aks[TK];
    __shared__ float  cadd;

    __nv_bfloat16* qWt = (__nv_bfloat16*)uraw;
    __nv_bfloat16* qt  = (__nv_bfloat16*)(uraw + TQ * PITCH * 2);
    uint*          GAs = (uint*)uraw;     // [16 k][64 row][4] f16x2 feature pairs

    const int tid  = threadIdx.x;
    const int warp = tid >> 5;
    const int lane = tid & 31;
    const int m    = lane & 3;
    const int g    = lane >> 2;
    const int wq   = warp & 3;
    const int wk   = warp >> 2;
    const int b    = blockIdx.z;
    const int q0   = blockIdx.y * TQ;
    const int k0   = blockIdx.x * TK;

    if (tid < GH) {
        int i = tid;
        int gq = b * Qn + q0 + i;
        cxq[i] = coords[gq * 2 + 0]; cyq[i] = coords[gq * 2 + 1];
        aqs[i] = amask[gq];
    } else if (tid < 2 * GH) {
        int i = tid - GH;
        int gk = b * Qn + k0 + i;
        cxk[i] = coords[gk * 2 + 0]; cyk[i] = coords[gk * 2 + 1];
        aks[i] = amask[gk];
    }
    if (tid == 0) cadd = b3[0] + bias[0];

    // layer-2 B fragment pairs (f16): entry (s, np, lane) -> frags n=2np, 2np+1
#pragma unroll
    for (int e = tid; e < 512; e += 256) {
        int s  = e >> 7;
        int np = (e >> 5) & 3;
        int ln = e & 31;
        int em = ln & 3, eg = ln >> 2;
        int kk = 16 * s + 2 * em;
        uint4 v;
        int n0 = 8 * (2 * np) + eg;
        v.x = packh2(w2[kk * GH + n0],       w2[(kk + 1) * GH + n0]);
        v.y = packh2(w2[(kk + 8) * GH + n0], w2[(kk + 9) * GH + n0]);
        int n1 = 8 * (2 * np + 1) + eg;
        v.z = packh2(w2[kk * GH + n1],       w2[(kk + 1) * GH + n1]);
        v.w = packh2(w2[(kk + 8) * GH + n1], w2[(kk + 9) * GH + n1]);
        B4s[e] = v;
    }
    if (tid < 32) {
        int nb = tid >> 2, mm = tid & 3;
        int c = 8 * nb + 2 * mm;
        b1ph[tid] = packh2(b1[c], b1[c + 1]);
        b2ph[tid] = packh2(b2[c], b2[c + 1]);
        w3ph[tid] = packh2(w3[c], w3[c + 1]);
    }

    uint W1B[8];
#pragma unroll
    for (int nb = 0; nb < 8; nb++) {
        int nn = 8 * nb + g;
        W1B[nb] = (m < 3) ? packh2(w1[(2 * m) * GH + nn], w1[(2 * m + 1) * GH + nn]) : 0u;
    }

    // ---- bilinear via bf16 mma (unchanged) ----
    float bacc[4][4];
#pragma unroll
    for (int n = 0; n < 4; n++)
#pragma unroll
        for (int j = 0; j < 4; j++) bacc[n][j] = 0.f;

#pragma unroll 1
    for (int d0 = 0; d0 < Dn; d0 += 64) {
        __syncthreads();
#pragma unroll
        for (int rep = 0; rep < 2; rep++) {
            int idx = tid + rep * 256;
            int r = idx >> 3, c8 = (idx & 7) * 8;
            *(uint4*)&qWt[r * PITCH + c8] =
                *(const uint4*)&g_qWb[(b * Qn + q0 + r) * Dn + d0 + c8];
            *(uint4*)&qt[r * PITCH + c8] =
                *(const uint4*)&g_qb[(b * Qn + k0 + r) * Dn + d0 + c8];
        }
        __syncthreads();
#pragma unroll
        for (int s2 = 0; s2 < 4; s2++) {
            const int acol = 16 * s2 + 2 * m;
            const int arow = 16 * wq + g;
            uint a0 = *(const uint*)&qWt[arow * PITCH + acol];
            uint a1 = *(const uint*)&qWt[(arow + 8) * PITCH + acol];
            uint a2 = *(const uint*)&qWt[arow * PITCH + acol + 8];
            uint a3 = *(const uint*)&qWt[(arow + 8) * PITCH + acol + 8];
#pragma unroll
            for (int n = 0; n < 4; n++) {
                const int brow = 32 * wk + 8 * n + g;
                uint b0 = *(const uint*)&qt[brow * PITCH + acol];
                uint b1v = *(const uint*)&qt[brow * PITCH + acol + 8];
                mma16816(bacc[n], a0, a1, a2, a3, b0, b1v);
            }
        }
    }
    __syncthreads();
#pragma unroll
    for (int n = 0; n < 4; n++) {
        int row = 16 * wq + g;
        int col = 32 * wk + 8 * n + 2 * m;
        *(float2*)&bilS[row * BPITCH + col]       = make_float2(bacc[n][0], bacc[n][1]);
        *(float2*)&bilS[(row + 8) * BPITCH + col] = make_float2(bacc[n][2], bacc[n][3]);
    }

    // ---- MLP phase: 4 passes of 16 k's; GA table overlays bilinear tiles ----
    const int row0 = 16 * wq + g;
    const int row1 = row0 + 8;
    const bool qa0 = (aqs[row0] != 0), qa1 = (aqs[row1] != 0);
    const float caddv = cadd;

#pragma unroll 1
    for (int p = 0; p < 4; p++) {
        __syncthreads();   // prior GA/tile reads done before overwrite
        // GA features (f16x2) for k in [16p, 16p+16), all 64 rows
#pragma unroll
        for (int r = 0; r < 4; r++) {
            int e   = tid + 256 * r;        // 0..1023
            int kl  = e >> 6;               // 0..15
            int row = e & 63;
            int k   = 16 * p + kl;
            if (aks[k] != 0) {
                float dxv = cxq[row] - cxk[k];
                float dyv = cyq[row] - cyk[k];
                float d2v = fmaf(dxv, dxv, dyv * dyv);
                float dsv = sqrtf(d2v + 1e-8f);
                bool  mzv = (fabsf(dxv) < 1e-6f) && (fabsf(dyv) < 1e-6f);
                float xsv = mzv ? 1e-6f : dxv;
                float ysv = mzv ? 1e-6f : dyv;
                float rhv = rsqrtf(fmaf(xsv, xsv, ysv * ysv));
                uint4 gv;
                gv.x = packh2(dxv, dyv);
                gv.y = packh2(dsv, d2v);
                gv.z = packh2(ysv * rhv, xsv * rhv);
                gv.w = 0u;
                *(uint4*)&GAs[(kl * 64 + row) * 4] = gv;
            }
        }
        __syncthreads();

#pragma unroll 1
        for (int i = 0; i < 8; i++) {
            const int kl = 8 * wk + i;
            const int k  = 16 * p + kl;
            const int gk = k0 + k;
            const int mw = i >> 1;          // writer lane in m-group

            if (aks[k] == 0) {
                if (m == mw) {
                    out[((long)(b * Qn + q0 + row0)) * Qn + gk] = -1e9f;
                    out[((long)(b * Qn + q0 + row1)) * Qn + gk] = -1e9f;
                }
                continue;
            }

            const uint GA0 = GAs[(kl * 64 + row0) * 4 + m];
            const uint GA1 = GAs[(kl * 64 + row1) * 4 + m];

            // layer-2 accumulators (f16x2, b2-initialized)
            uint acc2[8][2];
#pragma unroll
            for (int n = 0; n < 8; n++) {
                uint bv = b2ph[n * 4 + m];
                acc2[n][0] = bv;
                acc2[n][1] = bv;
            }

#pragma unroll
            for (int s = 0; s < 4; s++) {
                const uint bb0 = b1ph[(2 * s) * 4 + m];
                const uint bb1 = b1ph[(2 * s + 1) * 4 + m];
                uint d0 = bb0, d1 = bb0;
                mma16808h(d0, d1, GA0, GA1, W1B[2 * s]);
                uint e0 = bb1, e1 = bb1;
                mma16808h(e0, e1, GA0, GA1, W1B[2 * s + 1]);
                uint a0 = silu2h(d0);
                uint a1 = silu2h(d1);
                uint a2 = silu2h(e0);
                uint a3 = silu2h(e1);

                const uint4* Brow = &B4s[(s * 4) * 32 + lane];
#pragma unroll
                for (int np = 0; np < 4; np++) {
                    uint4 Bv = Brow[np * 32];
                    mma16816h(acc2[2 * np][0],     acc2[2 * np][1],
                              a0, a1, a2, a3, Bv.x, Bv.y);
                    mma16816h(acc2[2 * np + 1][0], acc2[2 * np + 1][1],
                              a0, a1, a2, a3, Bv.z, Bv.w);
                }
            }

            // epilogue: packed silu(h2) . w3 (silu directly on packed acc)
            uint P0 = 0u, P1 = 0u;
#pragma unroll
            for (int n = 0; n < 8; n++) {
                uint wv = w3ph[n * 4 + m];
                uint s01 = silu2h(acc2[n][0]);
                uint s23 = silu2h(acc2[n][1]);
                HFMA2H(P0, s01, wv, P0);
                HFMA2H(P1, s23, wv, P1);
            }
            float p0 = hsum2(P0);
            float p1 = hsum2(P1);
            p0 += __shfl_xor_sync(0xffffffffu, p0, 1);
            p0 += __shfl_xor_sync(0xffffffffu, p0, 2);
            p1 += __shfl_xor_sync(0xffffffffu, p1, 1);
            p1 += __shfl_xor_sync(0xffffffffu, p1, 2);

            if (m == mw) {
                const int qi0 = q0 + row0, qi1 = q0 + row1;
                float v0 = qa0 ? ((qi0 == gk) ? 0.f
                                  : p0 + bilS[row0 * BPITCH + k] + caddv) : -1e9f;
                float v1 = qa1 ? ((qi1 == gk) ? 0.f
                                  : p1 + bilS[row1 * BPITCH + k] + caddv) : -1e9f;
                out[((long)(b * Qn + qi0)) * Qn + gk] = v0;
                out[((long)(b * Qn + qi1)) * Qn + gk] = v1;
            }
        }
    }
}

// ---------------------------------------------------------------------------
extern "C" void kernel_launch(void* const* d_in, const int* in_sizes, int n_in,
                              void* d_out, int out_size)
{
    const float* q      = (const float*)d_in[0];
    const float* coords = (const float*)d_in[1];
    const int*   amask  = (const int*)d_in[2];
    const float* W      = (const float*)d_in[3];
    const float* w1     = (const float*)d_in[4];
    const float* b1     = (const float*)d_in[5];
    const float* w2     = (const float*)d_in[6];
    const float* b2     = (const float*)d_in[7];
    const float* w3     = (const float*)d_in[8];
    const float* b3     = (const float*)d_in[9];
    const float* bias   = (const float*)d_in[10];
    float* out = (float*)d_out;

    {
        dim3 grid((Bn * Qn) / 64, Dn / 64);
        prep_kernel<<<grid, 256>>>(q, W);
    }
    {
        dim3 grid(Qn / TK, Qn / TQ, Bn);
        edge_head_mma_kernel<<<grid, 256>>>(coords, amask,
                                            w1, b1, w2, b2, w3, b3, bias, out);
    }
}

// round 15
// speedup vs baseline: 1.3603x; 1.0116x over previous
#include <cuda_runtime.h>
#include <cuda_bf16.h>
#include <cuda_fp16.h>
#include <math.h>

#define Bn 4
#define Qn 1024
#define Dn 256
#define GH 64
#define TQ 64
#define TK 64
#define PITCH 72    // bf16 pitch for mma smem tiles
#define BPITCH 66   // fp32 pitch for bil staging

typedef unsigned int uint;

__device__ __nv_bfloat16 g_qWb[Bn * Qn * Dn];
__device__ __nv_bfloat16 g_qb[Bn * Qn * Dn];

__device__ __forceinline__ uint packbf2(float lo, float hi) {
    uint r;
    asm("cvt.rn.bf16x2.f32 %0, %1, %2;" : "=r"(r) : "f"(hi), "f"(lo));
    return r;
}

__device__ __forceinline__ uint packh2(float lo, float hi) {
    uint r;
    asm("cvt.rn.f16x2.f32 %0, %1, %2;" : "=r"(r) : "f"(hi), "f"(lo));
    return r;
}

// packed silu on f16x2 in 3 ops: u=0.5x; t=tanh(u); r=u*t+u  (= x*sigmoid(x))
__device__ __forceinline__ uint silu2h(uint x) {
    const uint H = 0x38003800u;   // f16x2 (0.5, 0.5)
    uint u, t, r;
    asm("mul.rn.f16x2 %0, %1, %2;" : "=r"(u) : "r"(x), "r"(H));
    asm("tanh.approx.f16x2 %0, %1;" : "=r"(t) : "r"(u));
    asm("fma.rn.f16x2 %0, %1, %2, %3;" : "=r"(r) : "r"(u), "r"(t), "r"(u));
    return r;
}

#define HFMA2H(d, a, b, c) \
    asm("fma.rn.f16x2 %0, %1, %2, %3;" : "=r"(d) : "r"(a), "r"(b), "r"(c))

__device__ __forceinline__ float hsum2(uint p) {
    float2 f = __half22float2(*(__half2*)&p);
    return f.x + f.y;
}

// bf16, f32-acc (bilinear / prep)
__device__ __forceinline__ void mma16816(float* c, uint a0, uint a1, uint a2, uint a3,
                                         uint b0, uint b1) {
    asm("mma.sync.aligned.m16n8k16.row.col.f32.bf16.bf16.f32 "
        "{%0,%1,%2,%3},{%4,%5,%6,%7},{%8,%9},{%0,%1,%2,%3};"
        : "+f"(c[0]), "+f"(c[1]), "+f"(c[2]), "+f"(c[3])
        : "r"(a0), "r"(a1), "r"(a2), "r"(a3), "r"(b0), "r"(b1));
}

// f16, f16-acc (MLP)
__device__ __forceinline__ void mma16816h(uint& d0, uint& d1,
                                          uint a0, uint a1, uint a2, uint a3,
                                          uint b0, uint b1) {
    asm("mma.sync.aligned.m16n8k16.row.col.f16.f16.f16.f16 "
        "{%0,%1},{%2,%3,%4,%5},{%6,%7},{%0,%1};"
        : "+r"(d0), "+r"(d1)
        : "r"(a0), "r"(a1), "r"(a2), "r"(a3), "r"(b0), "r"(b1));
}

__device__ __forceinline__ void mma16808h(uint& d0, uint& d1,
                                          uint a0, uint a1, uint b0) {
    asm("mma.sync.aligned.m16n8k8.row.col.f16.f16.f16.f16 "
        "{%0,%1},{%2,%3},{%4},{%0,%1};"
        : "+r"(d0), "+r"(d1)
        : "r"(a0), "r"(a1), "r"(b0));
}

// ---------------------------------------------------------------------------
// Fused prep kernel: qW = q @ W via mma; writes g_qWb (bf16); bn==0 blocks
// side-write g_qb. (unchanged)
// ---------------------------------------------------------------------------
__global__ __launch_bounds__(256) void prep_kernel(
    const float* __restrict__ q, const float* __restrict__ W)
{
    __shared__ __align__(16) __nv_bfloat16 At[64 * PITCH];
    __shared__ __align__(16) __nv_bfloat16 Bt[64 * PITCH];
    __shared__ __align__(16) float Ws[64][68];

    const int tid  = threadIdx.x;
    const int warp = tid >> 5;
    const int lane = tid & 31;
    const int m    = lane & 3;
    const int g    = lane >> 2;
    const int wq   = warp & 3;
    const int wk   = warp >> 2;
    const int bm   = blockIdx.x * 64;
    const int bn   = blockIdx.y * 64;

    float bacc[4][4];
#pragma unroll
    for (int n = 0; n < 4; n++)
#pragma unroll
        for (int j = 0; j < 4; j++) bacc[n][j] = 0.f;

#pragma unroll 1
    for (int k0 = 0; k0 < Dn; k0 += 64) {
        __syncthreads();
#pragma unroll
        for (int rep = 0; rep < 4; rep++) {
            int idx = rep * 256 + tid;
            int r = idx >> 4, c4 = idx & 15;
            float4 v = *(const float4*)&q[(bm + r) * Dn + k0 + c4 * 4];
            uint2 o;
            o.x = packbf2(v.x, v.y);
            o.y = packbf2(v.z, v.w);
            *(uint2*)&At[r * PITCH + c4 * 4] = o;
            if (bn == 0)
                *(uint2*)&g_qb[(bm + r) * Dn + k0 + c4 * 4] = o;
        }
#pragma unroll
        for (int rep = 0; rep < 4; rep++) {
            int idx = rep * 256 + tid;
            int kr = idx >> 4, nc4 = idx & 15;
            float4 w = *(const float4*)&W[(k0 + kr) * Dn + bn + nc4 * 4];
            *(float4*)&Ws[kr][nc4 * 4] = w;
        }
        __syncthreads();
#pragma unroll
        for (int rep = 0; rep < 8; rep++) {
            int idx = rep * 256 + tid;
            int nc = idx & 63, kp = idx >> 6;
            uint v = packbf2(Ws[2 * kp][nc], Ws[2 * kp + 1][nc]);
            *(uint*)&Bt[nc * PITCH + 2 * kp] = v;
        }
        __syncthreads();
#pragma unroll
        for (int s2 = 0; s2 < 4; s2++) {
            const int acol = 16 * s2 + 2 * m;
            const int arow = 16 * wq + g;
            uint a0 = *(const uint*)&At[arow * PITCH + acol];
            uint a1 = *(const uint*)&At[(arow + 8) * PITCH + acol];
            uint a2 = *(const uint*)&At[arow * PITCH + acol + 8];
            uint a3 = *(const uint*)&At[(arow + 8) * PITCH + acol + 8];
#pragma unroll
            for (int n = 0; n < 4; n++) {
                const int brow = 32 * wk + 8 * n + g;
                uint b0 = *(const uint*)&Bt[brow * PITCH + acol];
                uint b1 = *(const uint*)&Bt[brow * PITCH + acol + 8];
                mma16816(bacc[n], a0, a1, a2, a3, b0, b1);
            }
        }
    }
#pragma unroll
    for (int n = 0; n < 4; n++) {
        int row = bm + 16 * wq + g;
        int col = bn + 32 * wk + 8 * n + 2 * m;
        *(__nv_bfloat162*)&g_qWb[row * Dn + col] =
            __floats2bfloat162_rn(bacc[n][0], bacc[n][1]);
        *(__nv_bfloat162*)&g_qWb[(row + 8) * Dn + col] =
            __floats2bfloat162_rn(bacc[n][2], bacc[n][3]);
    }
}

// ---------------------------------------------------------------------------
// Fused kernel: bilinear (bf16 mma) + geo MLP (f16-acc mma, hoisted weights).
// ---------------------------------------------------------------------------
__global__ __launch_bounds__(256, 2) void edge_head_mma_kernel(
    const float* __restrict__ coords,
    const int*   __restrict__ amask,
    const float* __restrict__ w1,
    const float* __restrict__ b1,
    const float* __restrict__ w2,
    const float* __restrict__ b2,
    const float* __restrict__ w3,
    const float* __restrict__ b3,
    const float* __restrict__ bias,
    float* __restrict__ out)
{
    // union region: bilinear tiles (18432B) / GA feature table (16384B)
    __shared__ __align__(16) char uraw[TQ * PITCH * 2 + TK * PITCH * 2];
    __shared__ float  bilS[TQ * BPITCH];
    __shared__ __align__(16) uint4 B4s[4 * 4 * 32];   // layer-2 f16 B frag pairs
    __shared__ uint   b1ph[32], b2ph[32], w3ph[32];   // f16x2 packs [nb*4+m]
    __shared__ float  cxq[TQ], cyq[TQ], cxk[TK], cyk[TK];
    __shared__ int    aqs[TQ], aks[TK];
    __shared__ float  cadd;

    __nv_bfloat16* qWt = (__nv_bfloat16*)uraw;
    __nv_bfloat16* qt  = (__nv_bfloat16*)(uraw + TQ * PITCH * 2);
    uint*          GAs = (uint*)uraw;     // [16 k][64 row][4] f16x2 feature pairs

    const int tid  = threadIdx.x;
    const int warp = tid >> 5;
    const int lane = tid & 31;
    const int m    = lane & 3;
    const int g    = lane >> 2;
    const int wq   = warp & 3;
    const int wk   = warp >> 2;
    const int b    = blockIdx.z;
    const int q0   = blockIdx.y * TQ;
    const int k0   = blockIdx.x * TK;

    if (tid < GH) {
        int i = tid;
        int gq = b * Qn + q0 + i;
        cxq[i] = coords[gq * 2 + 0]; cyq[i] = coords[gq * 2 + 1];
        aqs[i] = amask[gq];
    } else if (tid < 2 * GH) {
        int i = tid - GH;
        int gk = b * Qn + k0 + i;
        cxk[i] = coords[gk * 2 + 0]; cyk[i] = coords[gk * 2 + 1];
        aks[i] = amask[gk];
    }
    if (tid == 0) cadd = b3[0] + bias[0];

    // layer-2 B fragment pairs (f16): entry (s, np, lane) -> frags n=2np, 2np+1
#pragma unroll
    for (int e = tid; e < 512; e += 256) {
        int s  = e >> 7;
        int np = (e >> 5) & 3;
        int ln = e & 31;
        int em = ln & 3, eg = ln >> 2;
        int kk = 16 * s + 2 * em;
        uint4 v;
        int n0 = 8 * (2 * np) + eg;
        v.x = packh2(w2[kk * GH + n0],       w2[(kk + 1) * GH + n0]);
        v.y = packh2(w2[(kk + 8) * GH + n0], w2[(kk + 9) * GH + n0]);
        int n1 = 8 * (2 * np + 1) + eg;
        v.z = packh2(w2[kk * GH + n1],       w2[(kk + 1) * GH + n1]);
        v.w = packh2(w2[(kk + 8) * GH + n1], w2[(kk + 9) * GH + n1]);
        B4s[e] = v;
    }
    if (tid < 32) {
        int nb = tid >> 2, mm = tid & 3;
        int c = 8 * nb + 2 * mm;
        b1ph[tid] = packh2(b1[c], b1[c + 1]);
        b2ph[tid] = packh2(b2[c], b2[c + 1]);
        w3ph[tid] = packh2(w3[c], w3[c + 1]);
    }

    uint W1B[8];
#pragma unroll
    for (int nb = 0; nb < 8; nb++) {
        int nn = 8 * nb + g;
        W1B[nb] = (m < 3) ? packh2(w1[(2 * m) * GH + nn], w1[(2 * m + 1) * GH + nn]) : 0u;
    }

    // ---- bilinear via bf16 mma ----
    float bacc[4][4];
#pragma unroll
    for (int n = 0; n < 4; n++)
#pragma unroll
        for (int j = 0; j < 4; j++) bacc[n][j] = 0.f;

#pragma unroll 1
    for (int d0 = 0; d0 < Dn; d0 += 64) {
        __syncthreads();
#pragma unroll
        for (int rep = 0; rep < 2; rep++) {
            int idx = tid + rep * 256;
            int r = idx >> 3, c8 = (idx & 7) * 8;
            *(uint4*)&qWt[r * PITCH + c8] =
                *(const uint4*)&g_qWb[(b * Qn + q0 + r) * Dn + d0 + c8];
            *(uint4*)&qt[r * PITCH + c8] =
                *(const uint4*)&g_qb[(b * Qn + k0 + r) * Dn + d0 + c8];
        }
        __syncthreads();
#pragma unroll
        for (int s2 = 0; s2 < 4; s2++) {
            const int acol = 16 * s2 + 2 * m;
            const int arow = 16 * wq + g;
            uint a0 = *(const uint*)&qWt[arow * PITCH + acol];
            uint a1 = *(const uint*)&qWt[(arow + 8) * PITCH + acol];
            uint a2 = *(const uint*)&qWt[arow * PITCH + acol + 8];
            uint a3 = *(const uint*)&qWt[(arow + 8) * PITCH + acol + 8];
#pragma unroll
            for (int n = 0; n < 4; n++) {
                const int brow = 32 * wk + 8 * n + g;
                uint b0 = *(const uint*)&qt[brow * PITCH + acol];
                uint b1v = *(const uint*)&qt[brow * PITCH + acol + 8];
                mma16816(bacc[n], a0, a1, a2, a3, b0, b1v);
            }
        }
    }
    __syncthreads();
#pragma unroll
    for (int n = 0; n < 4; n++) {
        int row = 16 * wq + g;
        int col = 32 * wk + 8 * n + 2 * m;
        *(float2*)&bilS[row * BPITCH + col]       = make_float2(bacc[n][0], bacc[n][1]);
        *(float2*)&bilS[(row + 8) * BPITCH + col] = make_float2(bacc[n][2], bacc[n][3]);
    }

    // ---- hoist loop-invariant per-thread weight packs (bacc now dead) ----
    uint B1R[8], W3R[8];
#pragma unroll
    for (int nb = 0; nb < 8; nb++) {
        B1R[nb] = b1ph[nb * 4 + m];
        W3R[nb] = w3ph[nb * 4 + m];
    }

    // ---- MLP phase: 4 passes of 16 k's; GA table overlays bilinear tiles ----
    const int row0 = 16 * wq + g;
    const int row1 = row0 + 8;
    const bool qa0 = (aqs[row0] != 0), qa1 = (aqs[row1] != 0);
    const float caddv = cadd;

#pragma unroll 1
    for (int p = 0; p < 4; p++) {
        __syncthreads();   // prior GA/tile reads done before overwrite
        // GA features (f16x2) for k in [16p, 16p+16), all 64 rows
#pragma unroll
        for (int r = 0; r < 4; r++) {
            int e   = tid + 256 * r;        // 0..1023
            int kl  = e >> 6;               // 0..15
            int row = e & 63;
            int k   = 16 * p + kl;
            if (aks[k] != 0) {
                float dxv = cxq[row] - cxk[k];
                float dyv = cyq[row] - cyk[k];
                float d2v = fmaf(dxv, dxv, dyv * dyv);
                float dsv = sqrtf(d2v + 1e-8f);
                bool  mzv = (fabsf(dxv) < 1e-6f) && (fabsf(dyv) < 1e-6f);
                float xsv = mzv ? 1e-6f : dxv;
                float ysv = mzv ? 1e-6f : dyv;
                float rhv = rsqrtf(fmaf(xsv, xsv, ysv * ysv));
                uint4 gv;
                gv.x = packh2(dxv, dyv);
                gv.y = packh2(dsv, d2v);
                gv.z = packh2(ysv * rhv, xsv * rhv);
                gv.w = 0u;
                *(uint4*)&GAs[(kl * 64 + row) * 4] = gv;
            }
        }
        __syncthreads();

#pragma unroll 1
        for (int i = 0; i < 8; i++) {
            const int kl = 8 * wk + i;
            const int k  = 16 * p + kl;
            const int gk = k0 + k;
            const int mw = i >> 1;          // writer lane in m-group

            if (aks[k] == 0) {
                if (m == mw) {
                    out[((long)(b * Qn + q0 + row0)) * Qn + gk] = -1e9f;
                    out[((long)(b * Qn + q0 + row1)) * Qn + gk] = -1e9f;
                }
                continue;
            }

            const uint GA0 = GAs[(kl * 64 + row0) * 4 + m];
            const uint GA1 = GAs[(kl * 64 + row1) * 4 + m];

            // layer-2 accumulators (f16x2, b2-initialized)
            uint acc2[8][2];
#pragma unroll
            for (int n = 0; n < 8; n++) {
                uint bv = b2ph[n * 4 + m];
                acc2[n][0] = bv;
                acc2[n][1] = bv;
            }

#pragma unroll
            for (int s = 0; s < 4; s++) {
                const uint bb0 = B1R[2 * s];
                const uint bb1 = B1R[2 * s + 1];
                uint d0 = bb0, d1 = bb0;
                mma16808h(d0, d1, GA0, GA1, W1B[2 * s]);
                uint e0 = bb1, e1 = bb1;
                mma16808h(e0, e1, GA0, GA1, W1B[2 * s + 1]);
                uint a0 = silu2h(d0);
                uint a1 = silu2h(d1);
                uint a2 = silu2h(e0);
                uint a3 = silu2h(e1);

                const uint4* Brow = &B4s[(s * 4) * 32 + lane];
#pragma unroll
                for (int np = 0; np < 4; np++) {
                    uint4 Bv = Brow[np * 32];
                    mma16816h(acc2[2 * np][0],     acc2[2 * np][1],
                              a0, a1, a2, a3, Bv.x, Bv.y);
                    mma16816h(acc2[2 * np + 1][0], acc2[2 * np + 1][1],
                              a0, a1, a2, a3, Bv.z, Bv.w);
                }
            }

            // epilogue: packed silu(h2) . w3 (silu directly on packed acc)
            uint P0 = 0u, P1 = 0u;
#pragma unroll
            for (int n = 0; n < 8; n++) {
                uint wv = W3R[n];
                uint s01 = silu2h(acc2[n][0]);
                uint s23 = silu2h(acc2[n][1]);
                HFMA2H(P0, s01, wv, P0);
                HFMA2H(P1, s23, wv, P1);
            }
            float p0 = hsum2(P0);
            float p1 = hsum2(P1);
            p0 += __shfl_xor_sync(0xffffffffu, p0, 1);
            p0 += __shfl_xor_sync(0xffffffffu, p0, 2);
            p1 += __shfl_xor_sync(0xffffffffu, p1, 1);
            p1 += __shfl_xor_sync(0xffffffffu, p1, 2);

            if (m == mw) {
                const int qi0 = q0 + row0, qi1 = q0 + row1;
                float v0 = qa0 ? ((qi0 == gk) ? 0.f
                                  : p0 + bilS[row0 * BPITCH + k] + caddv) : -1e9f;
                float v1 = qa1 ? ((qi1 == gk) ? 0.f
                                  : p1 + bilS[row1 * BPITCH + k] + caddv) : -1e9f;
                out[((long)(b * Qn + qi0)) * Qn + gk] = v0;
                out[((long)(b * Qn + qi1)) * Qn + gk] = v1;
            }
        }
    }
}

// ---------------------------------------------------------------------------
extern "C" void kernel_launch(void* const* d_in, const int* in_sizes, int n_in,
                              void* d_out, int out_size)
{
    const float* q      = (const float*)d_in[0];
    const float* coords = (const float*)d_in[1];
    const int*   amask  = (const int*)d_in[2];
    const float* W      = (const float*)d_in[3];
    const float* w1     = (const float*)d_in[4];
    const float* b1     = (const float*)d_in[5];
    const float* w2     = (const float*)d_in[6];
    const float* b2     = (const float*)d_in[7];
    const float* w3     = (const float*)d_in[8];
    const float* b3     = (const float*)d_in[9];
    const float* bias   = (const float*)d_in[10];
    float* out = (float*)d_out;

    {
        dim3 grid((Bn * Qn) / 64, Dn / 64);
        prep_kernel<<<grid, 256>>>(q, W);
    }
    {
        dim3 grid(Qn / TK, Qn / TQ, Bn);
        edge_head_mma_kernel<<<grid, 256>>>(coords, amask,
                                            w1, b1, w2, b2, w3, b3, bias, out);
    }
}

// round 16
// speedup vs baseline: 1.4595x; 1.0730x over previous
#include <cuda_runtime.h>
#include <cuda_bf16.h>
#include <cuda_fp16.h>
#include <math.h>

#define Bn 4
#define Qn 1024
#define Dn 256
#define GH 64
#define TQ 64
#define TK 64
#define PITCH 72    // bf16 pitch for mma smem tiles
#define BPITCH 66   // fp32 pitch for bil staging

typedef unsigned int uint;

__device__ __nv_bfloat16 g_qWb[Bn * Qn * Dn];
__device__ __nv_bfloat16 g_qb[Bn * Qn * Dn];

__device__ __forceinline__ uint packbf2(float lo, float hi) {
    uint r;
    asm("cvt.rn.bf16x2.f32 %0, %1, %2;" : "=r"(r) : "f"(hi), "f"(lo));
    return r;
}

__device__ __forceinline__ uint packh2(float lo, float hi) {
    uint r;
    asm("cvt.rn.f16x2.f32 %0, %1, %2;" : "=r"(r) : "f"(hi), "f"(lo));
    return r;
}

// packed silu on f16x2 in 3 ops: u=0.5x; t=tanh(u); r=u*t+u  (= x*sigmoid(x))
__device__ __forceinline__ uint silu2h(uint x) {
    const uint H = 0x38003800u;   // f16x2 (0.5, 0.5)
    uint u, t, r;
    asm("mul.rn.f16x2 %0, %1, %2;" : "=r"(u) : "r"(x), "r"(H));
    asm("tanh.approx.f16x2 %0, %1;" : "=r"(t) : "r"(u));
    asm("fma.rn.f16x2 %0, %1, %2, %3;" : "=r"(r) : "r"(u), "r"(t), "r"(u));
    return r;
}

#define HFMA2H(d, a, b, c) \
    asm("fma.rn.f16x2 %0, %1, %2, %3;" : "=r"(d) : "r"(a), "r"(b), "r"(c))

__device__ __forceinline__ float hsum2(uint p) {
    float2 f = __half22float2(*(__half2*)&p);
    return f.x + f.y;
}

// bf16, f32-acc (bilinear / prep)
__device__ __forceinline__ void mma16816(float* c, uint a0, uint a1, uint a2, uint a3,
                                         uint b0, uint b1) {
    asm("mma.sync.aligned.m16n8k16.row.col.f32.bf16.bf16.f32 "
        "{%0,%1,%2,%3},{%4,%5,%6,%7},{%8,%9},{%0,%1,%2,%3};"
        : "+f"(c[0]), "+f"(c[1]), "+f"(c[2]), "+f"(c[3])
        : "r"(a0), "r"(a1), "r"(a2), "r"(a3), "r"(b0), "r"(b1));
}

// f16, f16-acc (MLP)
__device__ __forceinline__ void mma16816h(uint& d0, uint& d1,
                                          uint a0, uint a1, uint a2, uint a3,
                                          uint b0, uint b1) {
    asm("mma.sync.aligned.m16n8k16.row.col.f16.f16.f16.f16 "
        "{%0,%1},{%2,%3,%4,%5},{%6,%7},{%0,%1};"
        : "+r"(d0), "+r"(d1)
        : "r"(a0), "r"(a1), "r"(a2), "r"(a3), "r"(b0), "r"(b1));
}

__device__ __forceinline__ void mma16808h(uint& d0, uint& d1,
                                          uint a0, uint a1, uint b0) {
    asm("mma.sync.aligned.m16n8k8.row.col.f16.f16.f16.f16 "
        "{%0,%1},{%2,%3},{%4},{%0,%1};"
        : "+r"(d0), "+r"(d1)
        : "r"(a0), "r"(a1), "r"(b0));
}

// ---------------------------------------------------------------------------
// Fused prep kernel: qW = q @ W via mma; writes g_qWb (bf16); bn==0 blocks
// side-write g_qb. (unchanged)
// ---------------------------------------------------------------------------
__global__ __launch_bounds__(256) void prep_kernel(
    const float* __restrict__ q, const float* __restrict__ W)
{
    __shared__ __align__(16) __nv_bfloat16 At[64 * PITCH];
    __shared__ __align__(16) __nv_bfloat16 Bt[64 * PITCH];
    __shared__ __align__(16) float Ws[64][68];

    const int tid  = threadIdx.x;
    const int warp = tid >> 5;
    const int lane = tid & 31;
    const int m    = lane & 3;
    const int g    = lane >> 2;
    const int wq   = warp & 3;
    const int wk   = warp >> 2;
    const int bm   = blockIdx.x * 64;
    const int bn   = blockIdx.y * 64;

    float bacc[4][4];
#pragma unroll
    for (int n = 0; n < 4; n++)
#pragma unroll
        for (int j = 0; j < 4; j++) bacc[n][j] = 0.f;

#pragma unroll 1
    for (int k0 = 0; k0 < Dn; k0 += 64) {
        __syncthreads();
#pragma unroll
        for (int rep = 0; rep < 4; rep++) {
            int idx = rep * 256 + tid;
            int r = idx >> 4, c4 = idx & 15;
            float4 v = *(const float4*)&q[(bm + r) * Dn + k0 + c4 * 4];
            uint2 o;
            o.x = packbf2(v.x, v.y);
            o.y = packbf2(v.z, v.w);
            *(uint2*)&At[r * PITCH + c4 * 4] = o;
            if (bn == 0)
                *(uint2*)&g_qb[(bm + r) * Dn + k0 + c4 * 4] = o;
        }
#pragma unroll
        for (int rep = 0; rep < 4; rep++) {
            int idx = rep * 256 + tid;
            int kr = idx >> 4, nc4 = idx & 15;
            float4 w = *(const float4*)&W[(k0 + kr) * Dn + bn + nc4 * 4];
            *(float4*)&Ws[kr][nc4 * 4] = w;
        }
        __syncthreads();
#pragma unroll
        for (int rep = 0; rep < 8; rep++) {
            int idx = rep * 256 + tid;
            int nc = idx & 63, kp = idx >> 6;
            uint v = packbf2(Ws[2 * kp][nc], Ws[2 * kp + 1][nc]);
            *(uint*)&Bt[nc * PITCH + 2 * kp] = v;
        }
        __syncthreads();
#pragma unroll
        for (int s2 = 0; s2 < 4; s2++) {
            const int acol = 16 * s2 + 2 * m;
            const int arow = 16 * wq + g;
            uint a0 = *(const uint*)&At[arow * PITCH + acol];
            uint a1 = *(const uint*)&At[(arow + 8) * PITCH + acol];
            uint a2 = *(const uint*)&At[arow * PITCH + acol + 8];
            uint a3 = *(const uint*)&At[(arow + 8) * PITCH + acol + 8];
#pragma unroll
            for (int n = 0; n < 4; n++) {
                const int brow = 32 * wk + 8 * n + g;
                uint b0 = *(const uint*)&Bt[brow * PITCH + acol];
                uint b1 = *(const uint*)&Bt[brow * PITCH + acol + 8];
                mma16816(bacc[n], a0, a1, a2, a3, b0, b1);
            }
        }
    }
#pragma unroll
    for (int n = 0; n < 4; n++) {
        int row = bm + 16 * wq + g;
        int col = bn + 32 * wk + 8 * n + 2 * m;
        *(__nv_bfloat162*)&g_qWb[row * Dn + col] =
            __floats2bfloat162_rn(bacc[n][0], bacc[n][1]);
        *(__nv_bfloat162*)&g_qWb[(row + 8) * Dn + col] =
            __floats2bfloat162_rn(bacc[n][2], bacc[n][3]);
    }
}

// ---------------------------------------------------------------------------
// Fused kernel: bilinear (bf16 mma) + geo MLP on COMPACTED active q-rows.
// ---------------------------------------------------------------------------
__global__ __launch_bounds__(256, 2) void edge_head_mma_kernel(
    const float* __restrict__ coords,
    const int*   __restrict__ amask,
    const float* __restrict__ w1,
    const float* __restrict__ b1,
    const float* __restrict__ w2,
    const float* __restrict__ b2,
    const float* __restrict__ w3,
    const float* __restrict__ b3,
    const float* __restrict__ bias,
    float* __restrict__ out)
{
    // union region: bilinear tiles (18432B) / GA feature table (16384B)
    __shared__ __align__(16) char uraw[TQ * PITCH * 2 + TK * PITCH * 2];
    __shared__ float  bilS[TQ * BPITCH];
    __shared__ __align__(16) uint4 B4s[4 * 4 * 32];   // layer-2 f16 B frag pairs
    __shared__ uint   b1ph[32], b2ph[32], w3ph[32];   // f16x2 packs [nb*4+m]
    __shared__ float  cxq[TQ], cyq[TQ], cxk[TK], cyk[TK];
    __shared__ int    aqs[TQ], aks[TK];
    __shared__ int    sActQ[TQ];
    __shared__ int    sRa;
    __shared__ float  cadd;

    __nv_bfloat16* qWt = (__nv_bfloat16*)uraw;
    __nv_bfloat16* qt  = (__nv_bfloat16*)(uraw + TQ * PITCH * 2);
    uint*          GAs = (uint*)uraw;     // [16 k][64 compact-row][4] f16x2 pairs

    const int tid  = threadIdx.x;
    const int warp = tid >> 5;
    const int lane = tid & 31;
    const int m    = lane & 3;
    const int g    = lane >> 2;
    const int wq   = warp & 3;
    const int wk   = warp >> 2;
    const int b    = blockIdx.z;
    const int q0   = blockIdx.y * TQ;
    const int k0   = blockIdx.x * TK;

    if (tid < GH) {
        int i = tid;
        int gq = b * Qn + q0 + i;
        cxq[i] = coords[gq * 2 + 0]; cyq[i] = coords[gq * 2 + 1];
        aqs[i] = amask[gq];
    } else if (tid < 2 * GH) {
        int i = tid - GH;
        int gk = b * Qn + k0 + i;
        cxk[i] = coords[gk * 2 + 0]; cyk[i] = coords[gk * 2 + 1];
        aks[i] = amask[gk];
    }
    if (tid == 0) cadd = b3[0] + bias[0];

    // layer-2 B fragment pairs (f16): entry (s, np, lane) -> frags n=2np, 2np+1
#pragma unroll
    for (int e = tid; e < 512; e += 256) {
        int s  = e >> 7;
        int np = (e >> 5) & 3;
        int ln = e & 31;
        int em = ln & 3, eg = ln >> 2;
        int kk = 16 * s + 2 * em;
        uint4 v;
        int n0 = 8 * (2 * np) + eg;
        v.x = packh2(w2[kk * GH + n0],       w2[(kk + 1) * GH + n0]);
        v.y = packh2(w2[(kk + 8) * GH + n0], w2[(kk + 9) * GH + n0]);
        int n1 = 8 * (2 * np + 1) + eg;
        v.z = packh2(w2[kk * GH + n1],       w2[(kk + 1) * GH + n1]);
        v.w = packh2(w2[(kk + 8) * GH + n1], w2[(kk + 9) * GH + n1]);
        B4s[e] = v;
    }
    if (tid < 32) {
        int nb = tid >> 2, mm = tid & 3;
        int c = 8 * nb + 2 * mm;
        b1ph[tid] = packh2(b1[c], b1[c + 1]);
        b2ph[tid] = packh2(b2[c], b2[c + 1]);
        w3ph[tid] = packh2(w3[c], w3[c + 1]);
    }

    uint W1B[8];
#pragma unroll
    for (int nb = 0; nb < 8; nb++) {
        int nn = 8 * nb + g;
        W1B[nb] = (m < 3) ? packh2(w1[(2 * m) * GH + nn], w1[(2 * m + 1) * GH + nn]) : 0u;
    }

    __syncthreads();   // aqs/aks ready

    // ---- compact active q-rows (warp 0), then pad to 64 ----
    if (warp == 0) {
        uint m0 = __ballot_sync(0xffffffffu, aqs[lane] != 0);
        uint m1 = __ballot_sync(0xffffffffu, aqs[lane + 32] != 0);
        int c0 = __popc(m0);
        if (m0 & (1u << lane)) sActQ[__popc(m0 & ((1u << lane) - 1u))] = lane;
        if (m1 & (1u << lane)) sActQ[c0 + __popc(m1 & ((1u << lane) - 1u))] = lane + 32;
        if (lane == 0) sRa = c0 + __popc(m1);
    }
    __syncthreads();
    const int Ra = sRa;
    if (tid < 64 && tid >= Ra) sActQ[tid] = (Ra > 0) ? sActQ[Ra - 1] : 0;
    // prewrite -1e9 rows for inactive q-rows (entire row of 64 k's)
    {
        int row = tid >> 2, cb = (tid & 3) * 16;
        if (aqs[row] == 0) {
            const float4 neg = make_float4(-1e9f, -1e9f, -1e9f, -1e9f);
            float* dst = &out[((long)(b * Qn + q0 + row)) * Qn + k0 + cb];
#pragma unroll
            for (int c = 0; c < 16; c += 4) *(float4*)(dst + c) = neg;
        }
    }
    __syncthreads();   // sActQ padding complete before use

    // ---- bilinear via bf16 mma ----
    float bacc[4][4];
#pragma unroll
    for (int n = 0; n < 4; n++)
#pragma unroll
        for (int j = 0; j < 4; j++) bacc[n][j] = 0.f;

#pragma unroll 1
    for (int d0 = 0; d0 < Dn; d0 += 64) {
        __syncthreads();
#pragma unroll
        for (int rep = 0; rep < 2; rep++) {
            int idx = tid + rep * 256;
            int r = idx >> 3, c8 = (idx & 7) * 8;
            *(uint4*)&qWt[r * PITCH + c8] =
                *(const uint4*)&g_qWb[(b * Qn + q0 + r) * Dn + d0 + c8];
            *(uint4*)&qt[r * PITCH + c8] =
                *(const uint4*)&g_qb[(b * Qn + k0 + r) * Dn + d0 + c8];
        }
        __syncthreads();
#pragma unroll
        for (int s2 = 0; s2 < 4; s2++) {
            const int acol = 16 * s2 + 2 * m;
            const int arow = 16 * wq + g;
            uint a0 = *(const uint*)&qWt[arow * PITCH + acol];
            uint a1 = *(const uint*)&qWt[(arow + 8) * PITCH + acol];
            uint a2 = *(const uint*)&qWt[arow * PITCH + acol + 8];
            uint a3 = *(const uint*)&qWt[(arow + 8) * PITCH + acol + 8];
#pragma unroll
            for (int n = 0; n < 4; n++) {
                const int brow = 32 * wk + 8 * n + g;
                uint b0 = *(const uint*)&qt[brow * PITCH + acol];
                uint b1v = *(const uint*)&qt[brow * PITCH + acol + 8];
                mma16816(bacc[n], a0, a1, a2, a3, b0, b1v);
            }
        }
    }
    __syncthreads();
#pragma unroll
    for (int n = 0; n < 4; n++) {
        int row = 16 * wq + g;
        int col = 32 * wk + 8 * n + 2 * m;
        *(float2*)&bilS[row * BPITCH + col]       = make_float2(bacc[n][0], bacc[n][1]);
        *(float2*)&bilS[(row + 8) * BPITCH + col] = make_float2(bacc[n][2], bacc[n][3]);
    }

    // ---- hoist loop-invariant per-thread weight packs ----
    uint B1R[8], W3R[8];
#pragma unroll
    for (int nb = 0; nb < 8; nb++) {
        B1R[nb] = b1ph[nb * 4 + m];
        W3R[nb] = w3ph[nb * 4 + m];
    }

    // ---- MLP phase: compacted rows; this warp's rows fixed ----
    const int rc0  = 16 * wq + g;          // compact slots
    const int rc1  = rc0 + 8;
    const int row0 = sActQ[rc0];           // original tile rows (padded dup ok)
    const int row1 = sActQ[rc1];
    const bool chunkActive = (16 * wq < Ra);
    const float caddv = cadd;

#pragma unroll 1
    for (int p = 0; p < 4; p++) {
        __syncthreads();   // prior GA/tile reads done before overwrite
        // GA features (f16x2) for k in [16p, 16p+16), compacted rows 0..63
#pragma unroll
        for (int r = 0; r < 4; r++) {
            int e   = tid + 256 * r;        // 0..1023
            int kl  = e >> 6;               // 0..15
            int rc  = e & 63;               // compact slot
            int k   = 16 * p + kl;
            if (aks[k] != 0) {
                int row = sActQ[rc];
                float dxv = cxq[row] - cxk[k];
                float dyv = cyq[row] - cyk[k];
                float d2v = fmaf(dxv, dxv, dyv * dyv);
                float dsv = sqrtf(d2v + 1e-8f);
                bool  mzv = (fabsf(dxv) < 1e-6f) && (fabsf(dyv) < 1e-6f);
                float xsv = mzv ? 1e-6f : dxv;
                float ysv = mzv ? 1e-6f : dyv;
                float rhv = rsqrtf(fmaf(xsv, xsv, ysv * ysv));
                uint4 gv;
                gv.x = packh2(dxv, dyv);
                gv.y = packh2(dsv, d2v);
                gv.z = packh2(ysv * rhv, xsv * rhv);
                gv.w = 0u;
                *(uint4*)&GAs[(kl * 64 + rc) * 4] = gv;
            }
        }
        __syncthreads();

        if (!chunkActive) continue;   // whole chunk beyond Ra: no rows to do

#pragma unroll 1
        for (int i = 0; i < 8; i++) {
            const int kl = 8 * wk + i;
            const int k  = 16 * p + kl;
            const int gk = k0 + k;
            const int mw = i >> 1;          // writer lane in m-group

            if (aks[k] == 0) {
                if (m == mw) {
                    out[((long)(b * Qn + q0 + row0)) * Qn + gk] = -1e9f;
                    out[((long)(b * Qn + q0 + row1)) * Qn + gk] = -1e9f;
                }
                continue;
            }

            const uint GA0 = GAs[(kl * 64 + rc0) * 4 + m];
            const uint GA1 = GAs[(kl * 64 + rc1) * 4 + m];

            // layer-2 accumulators (f16x2, b2-initialized)
            uint acc2[8][2];
#pragma unroll
            for (int n = 0; n < 8; n++) {
                uint bv = b2ph[n * 4 + m];
                acc2[n][0] = bv;
                acc2[n][1] = bv;
            }

#pragma unroll
            for (int s = 0; s < 4; s++) {
                const uint bb0 = B1R[2 * s];
                const uint bb1 = B1R[2 * s + 1];
                uint d0 = bb0, d1 = bb0;
                mma16808h(d0, d1, GA0, GA1, W1B[2 * s]);
                uint e0 = bb1, e1 = bb1;
                mma16808h(e0, e1, GA0, GA1, W1B[2 * s + 1]);
                uint a0 = silu2h(d0);
                uint a1 = silu2h(d1);
                uint a2 = silu2h(e0);
                uint a3 = silu2h(e1);

                const uint4* Brow = &B4s[(s * 4) * 32 + lane];
#pragma unroll
                for (int np = 0; np < 4; np++) {
                    uint4 Bv = Brow[np * 32];
                    mma16816h(acc2[2 * np][0],     acc2[2 * np][1],
                              a0, a1, a2, a3, Bv.x, Bv.y);
                    mma16816h(acc2[2 * np + 1][0], acc2[2 * np + 1][1],
                              a0, a1, a2, a3, Bv.z, Bv.w);
                }
            }

            // epilogue: packed silu(h2) . w3
            uint P0 = 0u, P1 = 0u;
#pragma unroll
            for (int n = 0; n < 8; n++) {
                uint wv = W3R[n];
                uint s01 = silu2h(acc2[n][0]);
                uint s23 = silu2h(acc2[n][1]);
                HFMA2H(P0, s01, wv, P0);
                HFMA2H(P1, s23, wv, P1);
            }
            float p0 = hsum2(P0);
            float p1 = hsum2(P1);
            p0 += __shfl_xor_sync(0xffffffffu, p0, 1);
            p0 += __shfl_xor_sync(0xffffffffu, p0, 2);
            p1 += __shfl_xor_sync(0xffffffffu, p1, 1);
            p1 += __shfl_xor_sync(0xffffffffu, p1, 2);

            if (m == mw) {
                const int qi0 = q0 + row0, qi1 = q0 + row1;
                out[((long)(b * Qn + qi0)) * Qn + gk] =
                    (qi0 == gk) ? 0.f : p0 + bilS[row0 * BPITCH + k] + caddv;
                out[((long)(b * Qn + qi1)) * Qn + gk] =
                    (qi1 == gk) ? 0.f : p1 + bilS[row1 * BPITCH + k] + caddv;
            }
        }
    }
}

// ---------------------------------------------------------------------------
extern "C" void kernel_launch(void* const* d_in, const int* in_sizes, int n_in,
                              void* d_out, int out_size)
{
    const float* q      = (const float*)d_in[0];
    const float* coords = (const float*)d_in[1];
    const int*   amask  = (const int*)d_in[2];
    const float* W      = (const float*)d_in[3];
    const float* w1     = (const float*)d_in[4];
    const float* b1     = (const float*)d_in[5];
    const float* w2     = (const float*)d_in[6];
    const float* b2     = (const float*)d_in[7];
    const float* w3     = (const float*)d_in[8];
    const float* b3     = (const float*)d_in[9];
    const float* bias   = (const float*)d_in[10];
    float* out = (float*)d_out;

    {
        dim3 grid((Bn * Qn) / 64, Dn / 64);
        prep_kernel<<<grid, 256>>>(q, W);
    }
    {
        dim3 grid(Qn / TK, Qn / TQ, Bn);
        edge_head_mma_kernel<<<grid, 256>>>(coords, amask,
                                            w1, b1, w2, b2, w3, b3, bias, out);
    }
}